// round 13
// baseline (speedup 1.0000x reference)
#include <cuda_runtime.h>
#include <cuda_bf16.h>
#include <cstdint>

#define NMAX 50000
#define EMAX 800000
#define HID 128
#define H 8
#define D 16
#define ALPHA 0.2f
#define BN_EPS 1e-5f

// ---------------- scratch (static device globals; no allocation) ----------------
__device__ float d_h[NMAX * HID];        // post-GEMM features for current layer
__device__ float d_aggb[3][NMAX * HID];  // per-layer normalized aggregation
__device__ float d_esrc[NMAX * H];
__device__ float d_edst[NMAX * H];
__device__ float d_gsum[HID];
__device__ float d_gsq[HID];
__device__ float d_scs[3][HID];          // folded BN scale per layer
__device__ float d_shs[3][HID];          // folded BN shift per layer
__device__ int   d_rowptr[NMAX + 1];     // CSR by dst
__device__ int   d_cursor[NMAX];
__device__ int   d_csrc[EMAX];

__device__ __forceinline__ float eluf(float y) {
    return (y > 0.f) ? y : expm1f(y);
}

// =================================================================================
// GEMM: d_h[n,128] = act(A)[n,128] @ B[128,128], tf32 mma.sync 3-term split.
// GKC=8 single-buffered -> 17.4 KB smem -> 2 CTAs/SM (occupancy x2): the peer
// CTA's MMA phase covers this CTA's stage/barrier stalls.
// mode 0: act = identity; mode 1: act = elu(bn_{b1i}(A1));
// mode 2: act = elu(bn_{b1i}(A1)) + elu(bn_{b2i}(A2))   (skip connection)
// =================================================================================
__device__ __forceinline__ uint32_t f2tf(float f) {
    uint32_t u;
    asm("cvt.rna.tf32.f32 %0, %1;" : "=r"(u) : "f"(f));
    return u;
}

#define MMA8(c, a, b0, b1)                                                         \
    asm volatile("mma.sync.aligned.m16n8k8.row.col.f32.tf32.tf32.f32 "             \
                 "{%0,%1,%2,%3},{%4,%5,%6,%7},{%8,%9},{%0,%1,%2,%3};"              \
                 : "+f"(c[0]), "+f"(c[1]), "+f"(c[2]), "+f"(c[3])                  \
                 : "r"(a[0]), "r"(a[1]), "r"(a[2]), "r"(a[3]), "r"(b0), "r"(b1))

#define GKC 8
#define SSTR 136   // (136*k+grp) mod 32 = 8*k+grp -> conflict-free

__global__ __launch_bounds__(256, 2) void gemm_tc_kernel(const float* __restrict__ A1,
                                                         const float* __restrict__ A2,
                                                         const float* __restrict__ B,
                                                         int n, int mode, int b1i, int b2i) {
    __shared__ uint32_t Ah[GKC][SSTR], Al[GKC][SSTR];
    __shared__ uint32_t Bh[GKC][SSTR], Bl[GKC][SSTR];
    int tid  = threadIdx.x;
    int lane = tid & 31, warp = tid >> 5;
    int wm = warp >> 1, wn = warp & 1;          // warp tile: 32 rows x 64 cols
    int grp = lane >> 2, ktid = lane & 3;
    int row0 = blockIdx.x * 128;

    float acc[2][8][4];
#pragma unroll
    for (int t = 0; t < 2; t++)
#pragma unroll
        for (int j = 0; j < 8; j++)
#pragma unroll
            for (int q = 0; q < 4; q++) acc[t][j][q] = 0.f;

    int ar = tid & 127, aq = tid >> 7;          // A loader: row ar, col half aq
    int bkr = tid >> 5, bc = (tid & 31) * 4;    // B loader: k-row bkr, col bc
    bool arow_ok = (row0 + ar < n);

    for (int k0 = 0; k0 < HID; k0 += GKC) {
        // ---- stage A chunk [128 rows x 8 k] with fused activation, split hi/lo ----
        {
            int c = k0 + aq * 4;
            float4 v = make_float4(0.f, 0.f, 0.f, 0.f);
            if (arow_ok) {
                v = *(const float4*)&A1[(row0 + ar) * HID + c];
                if (mode >= 1) {
                    float4 sc = *(const float4*)&d_scs[b1i][c];
                    float4 sh = *(const float4*)&d_shs[b1i][c];
                    v.x = eluf(fmaf(v.x, sc.x, sh.x));
                    v.y = eluf(fmaf(v.y, sc.y, sh.y));
                    v.z = eluf(fmaf(v.z, sc.z, sh.z));
                    v.w = eluf(fmaf(v.w, sc.w, sh.w));
                    if (mode == 2) {
                        float4 v2  = *(const float4*)&A2[(row0 + ar) * HID + c];
                        float4 sc2 = *(const float4*)&d_scs[b2i][c];
                        float4 sh2 = *(const float4*)&d_shs[b2i][c];
                        v.x += eluf(fmaf(v2.x, sc2.x, sh2.x));
                        v.y += eluf(fmaf(v2.y, sc2.y, sh2.y));
                        v.z += eluf(fmaf(v2.z, sc2.z, sh2.z));
                        v.w += eluf(fmaf(v2.w, sc2.w, sh2.w));
                    }
                }
            }
            float fv[4] = {v.x, v.y, v.z, v.w};
#pragma unroll
            for (int e2 = 0; e2 < 4; e2++) {
                uint32_t hi = f2tf(fv[e2]);
                uint32_t lo = f2tf(fv[e2] - __uint_as_float(hi));
                Ah[aq * 4 + e2][ar] = hi;
                Al[aq * 4 + e2][ar] = lo;
            }
        }
        // ---- stage B chunk [8 k x 128 cols], split hi/lo ----
        {
            float4 bv = *(const float4*)&B[(k0 + bkr) * HID + bc];
            float fb[4] = {bv.x, bv.y, bv.z, bv.w};
            uint4 hv, lv;
            uint32_t* hp = (uint32_t*)&hv;
            uint32_t* lp = (uint32_t*)&lv;
#pragma unroll
            for (int e2 = 0; e2 < 4; e2++) {
                hp[e2] = f2tf(fb[e2]);
                lp[e2] = f2tf(fb[e2] - __uint_as_float(hp[e2]));
            }
            *(uint4*)&Bh[bkr][bc] = hv;
            *(uint4*)&Bl[bkr][bc] = lv;
        }
        __syncthreads();

        // ---- one k=8 MMA slab ----
        {
            uint32_t ah[2][4], al[2][4];
#pragma unroll
            for (int t = 0; t < 2; t++) {
                int m = wm * 32 + t * 16 + grp;
                ah[t][0] = Ah[ktid][m];
                ah[t][1] = Ah[ktid][m + 8];
                ah[t][2] = Ah[ktid + 4][m];
                ah[t][3] = Ah[ktid + 4][m + 8];
                al[t][0] = Al[ktid][m];
                al[t][1] = Al[ktid][m + 8];
                al[t][2] = Al[ktid + 4][m];
                al[t][3] = Al[ktid + 4][m + 8];
            }
#pragma unroll
            for (int j = 0; j < 8; j++) {
                int nn = wn * 64 + j * 8 + grp;
                uint32_t bh0 = Bh[ktid][nn], bh1 = Bh[ktid + 4][nn];
                uint32_t bl0 = Bl[ktid][nn], bl1 = Bl[ktid + 4][nn];
#pragma unroll
                for (int t = 0; t < 2; t++) {
                    MMA8(acc[t][j], ah[t], bh0, bh1);   // hi*hi
                    MMA8(acc[t][j], ah[t], bl0, bl1);   // hi*lo
                    MMA8(acc[t][j], al[t], bh0, bh1);   // lo*hi
                }
            }
        }
        __syncthreads();
    }

#pragma unroll
    for (int t = 0; t < 2; t++) {
        int r0 = row0 + wm * 32 + t * 16 + grp;
#pragma unroll
        for (int j = 0; j < 8; j++) {
            int c = wn * 64 + j * 8 + ktid * 2;
            if (r0 < n)
                *(float2*)&d_h[r0 * HID + c] = make_float2(acc[t][j][0], acc[t][j][1]);
            if (r0 + 8 < n)
                *(float2*)&d_h[(r0 + 8) * HID + c] = make_float2(acc[t][j][2], acc[t][j][3]);
        }
    }
}

// ---------------- attention coefficients + BN-stat reset -------------------------
__global__ void attn_kernel(const float* __restrict__ a, int n) {
    int t = blockIdx.x * blockDim.x + threadIdx.x;
    if (t < HID) { d_gsum[t] = 0.f; d_gsq[t] = 0.f; }
    if (t >= n * H) return;
    int node = t >> 3, head = t & 7;
    const float4* hp = (const float4*)(d_h + node * HID + head * D);
    const float4* ap = (const float4*)(a + head * 2 * D);
    float s1 = 0.f, s2 = 0.f;
#pragma unroll
    for (int i = 0; i < 4; i++) {
        float4 hv = hp[i];
        float4 a1v = __ldg(&ap[i]);
        float4 a2v = __ldg(&ap[4 + i]);
        s1 = fmaf(hv.x, a1v.x, fmaf(hv.y, a1v.y, fmaf(hv.z, a1v.z, fmaf(hv.w, a1v.w, s1))));
        s2 = fmaf(hv.x, a2v.x, fmaf(hv.y, a2v.y, fmaf(hv.z, a2v.z, fmaf(hv.w, a2v.w, s2))));
    }
    d_esrc[t] = s1;
    d_edst[t] = s2;
}

// ---------------- CSR construction (once per launch) -----------------------------
__global__ void hist_kernel(const int* __restrict__ ei, int e) {
    int t = blockIdx.x * blockDim.x + threadIdx.x;
    if (t < e) atomicAdd(&d_cursor[__ldg(&ei[e + t])], 1);
}

__global__ void scan_kernel(int n) {
    __shared__ int wsum[32];
    int tid = threadIdx.x;                 // 1024 threads, 1 block
    int lane = tid & 31, wid = tid >> 5;
    int chunk = (n + 1023) / 1024;
    int lo = tid * chunk;
    int hi = min(lo + chunk, n);
    int s = 0;
    for (int i = lo; i < hi; i++) s += d_cursor[i];
    int inc = s;
#pragma unroll
    for (int o = 1; o < 32; o <<= 1) {
        int v = __shfl_up_sync(~0u, inc, o);
        if (lane >= o) inc += v;
    }
    if (lane == 31) wsum[wid] = inc;
    __syncthreads();
    if (wid == 0) {
        int v = wsum[lane];
        int iv = v;
#pragma unroll
        for (int o = 1; o < 32; o <<= 1) {
            int u = __shfl_up_sync(~0u, iv, o);
            if (lane >= o) iv += u;
        }
        wsum[lane] = iv - v;
    }
    __syncthreads();
    int off = wsum[wid] + inc - s;
    for (int i = lo; i < hi; i++) {
        int c = d_cursor[i];
        d_rowptr[i] = off;
        d_cursor[i] = off;
        off += c;
    }
    if (hi == n) d_rowptr[n] = off;
}

__global__ void scatter_kernel(const int* __restrict__ ei, int e) {
    int t = blockIdx.x * blockDim.x + threadIdx.x;
    if (t >= e) return;
    int dst = __ldg(&ei[e + t]);
    int pos = atomicAdd(&d_cursor[dst], 1);
    d_csrc[pos] = __ldg(&ei[t]);
}

// ---------------- fused GAT aggregation: one warp per dst node -------------------
// Single pass (no softmax max: ratio is shift-invariant, exp finite here).
// Also accumulates per-channel BN sums via block reduction. (Round-8 form.)
__global__ __launch_bounds__(256) void agg_kernel(float* __restrict__ aggout, int n) {
    __shared__ float rsum[8][HID];
    int wid = threadIdx.x >> 5, lane = threadIdx.x & 31;
    int w = blockIdx.x * 8 + wid;
    int head = lane >> 2;
    float4 o = make_float4(0.f, 0.f, 0.f, 0.f);

    if (w < n) {
        int start = d_rowptr[w], end = d_rowptr[w + 1];
        float ed = d_edst[w * H + head];
        float4 acc = make_float4(0.f, 0.f, 0.f, 0.f);
        float den = 0.f;
        int i = start;
        for (; i + 2 <= end; i += 2) {               // 2 edges in flight
            int s0 = __ldg(&d_csrc[i]);
            int s1 = __ldg(&d_csrc[i + 1]);
            float e0 = d_esrc[s0 * H + head] + ed;
            float e1 = d_esrc[s1 * H + head] + ed;
            float4 h0 = *(const float4*)&d_h[s0 * HID + lane * 4];
            float4 h1 = *(const float4*)&d_h[s1 * HID + lane * 4];
            e0 = (e0 >= 0.f) ? e0 : ALPHA * e0;
            e1 = (e1 >= 0.f) ? e1 : ALPHA * e1;
            float w0 = __expf(e0), w1 = __expf(e1);
            acc.x = fmaf(h0.x, w0, fmaf(h1.x, w1, acc.x));
            acc.y = fmaf(h0.y, w0, fmaf(h1.y, w1, acc.y));
            acc.z = fmaf(h0.z, w0, fmaf(h1.z, w1, acc.z));
            acc.w = fmaf(h0.w, w0, fmaf(h1.w, w1, acc.w));
            den += w0 + w1;
        }
        if (i < end) {
            int s0 = __ldg(&d_csrc[i]);
            float e0 = d_esrc[s0 * H + head] + ed;
            float4 h0 = *(const float4*)&d_h[s0 * HID + lane * 4];
            e0 = (e0 >= 0.f) ? e0 : ALPHA * e0;
            float w0 = __expf(e0);
            acc.x = fmaf(h0.x, w0, acc.x);
            acc.y = fmaf(h0.y, w0, acc.y);
            acc.z = fmaf(h0.z, w0, acc.z);
            acc.w = fmaf(h0.w, w0, acc.w);
            den += w0;
        }
        float inv = 1.f / (den + 1e-16f);
        o = make_float4(acc.x * inv, acc.y * inv, acc.z * inv, acc.w * inv);
        *(float4*)&aggout[w * HID + lane * 4] = o;
    }

    // per-block BN stat reduction (zeros from inactive warps are harmless)
    *(float4*)&rsum[wid][lane * 4] = o;
    __syncthreads();
    if (threadIdx.x < HID) {
        int c = threadIdx.x;
        float s = 0.f, q = 0.f;
#pragma unroll
        for (int k = 0; k < 8; k++) {
            float v = rsum[k][c];
            s += v;
            q = fmaf(v, v, q);
        }
        atomicAdd(&d_gsum[c], s);
        atomicAdd(&d_gsq[c], q);
    }
}

// ---------------- fold BN stats into per-channel scale/shift ---------------------
__global__ void bnpar_kernel(const float* __restrict__ g, const float* __restrict__ b,
                             int idx, float invn) {
    int c = threadIdx.x;
    float mu = d_gsum[c] * invn;
    float var = d_gsq[c] * invn - mu * mu;
    float sc = g[c] * rsqrtf(var + BN_EPS);
    d_scs[idx][c] = sc;
    d_shs[idx][c] = b[c] - mu * sc;
}

// ---------------- final output: out = bn3(agg3) ----------------------------------
__global__ void out_kernel(const float* __restrict__ agg, float* __restrict__ out, int n) {
    int t = blockIdx.x * blockDim.x + threadIdx.x;
    if (t >= n * (HID / 4)) return;
    float4 v  = ((const float4*)agg)[t];
    int c = (t * 4) & (HID - 1);
    float4 sc = *(const float4*)&d_scs[2][c];
    float4 sh = *(const float4*)&d_shs[2][c];
    ((float4*)out)[t] = make_float4(fmaf(v.x, sc.x, sh.x), fmaf(v.y, sc.y, sh.y),
                                    fmaf(v.z, sc.z, sh.z), fmaf(v.w, sc.w, sh.w));
}

// ---------------- host-side driver -----------------------------------------------
extern "C" void kernel_launch(void* const* d_in, const int* in_sizes, int n_in,
                              void* d_out, int out_size) {
    const float* x  = (const float*)d_in[0];
    const int*   ei = (const int*)  d_in[1];
    const float* W1 = (const float*)d_in[2];
    const float* a1 = (const float*)d_in[3];
    const float* W2 = (const float*)d_in[4];
    const float* a2 = (const float*)d_in[5];
    const float* W3 = (const float*)d_in[6];
    const float* a3 = (const float*)d_in[7];
    const float* g1 = (const float*)d_in[8];
    const float* b1 = (const float*)d_in[9];
    const float* g2 = (const float*)d_in[10];
    const float* b2 = (const float*)d_in[11];
    const float* g3 = (const float*)d_in[12];
    const float* b3 = (const float*)d_in[13];

    int n = in_sizes[0] / HID;
    int e = in_sizes[1] / 2;
    float invn = 1.f / (float)n;

    float* aggbase = nullptr;
    void* curp = nullptr;
    cudaGetSymbolAddress((void**)&aggbase, d_aggb);
    cudaGetSymbolAddress(&curp, d_cursor);
    float* agg1 = aggbase;
    float* agg2 = aggbase + (size_t)NMAX * HID;
    float* agg3 = aggbase + (size_t)2 * NMAX * HID;

    // ---- build dst-CSR once; reused by all 3 layers ----
    cudaMemsetAsync(curp, 0, n * sizeof(int));
    hist_kernel<<<(e + 255) / 256, 256>>>(ei, e);
    scan_kernel<<<1, 1024>>>(n);
    scatter_kernel<<<(e + 255) / 256, 256>>>(ei, e);

    int gblk = (n + 127) / 128;
    int ablk = (n * H + 255) / 256;
    int wblk = (n + 7) / 8;

    // layer 1
    gemm_tc_kernel<<<gblk, 256>>>(x, nullptr, W1, n, 0, 0, 0);
    attn_kernel<<<ablk, 256>>>(a1, n);
    agg_kernel<<<wblk, 256>>>(agg1, n);
    bnpar_kernel<<<1, HID>>>(g1, b1, 0, invn);
    // layer 2 (input = elu(bn1(agg1)) computed in GEMM loader)
    gemm_tc_kernel<<<gblk, 256>>>(agg1, nullptr, W2, n, 1, 0, 0);
    attn_kernel<<<ablk, 256>>>(a2, n);
    agg_kernel<<<wblk, 256>>>(agg2, n);
    bnpar_kernel<<<1, HID>>>(g2, b2, 1, invn);
    // layer 3 (input = elu(bn1(agg1)) + elu(bn2(agg2)) in GEMM loader)
    gemm_tc_kernel<<<gblk, 256>>>(agg1, agg2, W3, n, 2, 0, 1);
    attn_kernel<<<ablk, 256>>>(a3, n);
    agg_kernel<<<wblk, 256>>>(agg3, n);
    bnpar_kernel<<<1, HID>>>(g3, b3, 2, invn);
    out_kernel<<<(n * (HID / 4) + 255) / 256, 256>>>(agg3, (float*)d_out, n);
}

// round 16
// speedup vs baseline: 1.1272x; 1.1272x over previous
#include <cuda_runtime.h>
#include <cuda_bf16.h>
#include <cstdint>

#define NMAX 50000
#define EMAX 800000
#define HID 128
#define H 8
#define D 16
#define ALPHA 0.2f
#define BN_EPS 1e-5f

// ---------------- scratch (static device globals; no allocation) ----------------
__device__ float d_h[NMAX * HID];        // post-GEMM features for current layer
__device__ float d_aggb[3][NMAX * HID];  // per-layer normalized aggregation
__device__ float d_esrc[NMAX * H];
__device__ float d_edst[NMAX * H];
__device__ float d_gsum[HID];            // zero at load; re-zeroed by bnpar after use
__device__ float d_gsq[HID];
__device__ float d_scs[3][HID];          // folded BN scale per layer
__device__ float d_shs[3][HID];          // folded BN shift per layer
__device__ int   d_rowptr[NMAX + 1];     // CSR by dst
__device__ int   d_cursor[NMAX];
__device__ int   d_csrc[EMAX];

__device__ __forceinline__ float eluf(float y) {
    return (y > 0.f) ? y : expm1f(y);
}

// =================================================================================
// GEMM: d_h[n,128] = act(A)[n,128] @ B[128,128], tf32 mma.sync 3-term split,
// with FUSED attention epilogue: each warp's fragment covers 4 complete heads
// (16 cols each), so esrc/edst = sum(h*a) is computed in-register + shfl-reduced.
// mode 0: act = identity (raw x)
// mode 1: act = elu(bn_{b1i}(A1))
// mode 2: act = elu(bn_{b1i}(A1)) + elu(bn_{b2i}(A2))   (skip connection)
// =================================================================================
__device__ __forceinline__ uint32_t f2tf(float f) {
    uint32_t u;
    asm("cvt.rna.tf32.f32 %0, %1;" : "=r"(u) : "f"(f));
    return u;
}

#define MMA8(c, a, b0, b1)                                                         \
    asm volatile("mma.sync.aligned.m16n8k8.row.col.f32.tf32.tf32.f32 "             \
                 "{%0,%1,%2,%3},{%4,%5,%6,%7},{%8,%9},{%0,%1,%2,%3};"              \
                 : "+f"(c[0]), "+f"(c[1]), "+f"(c[2]), "+f"(c[3])                  \
                 : "r"(a[0]), "r"(a[1]), "r"(a[2]), "r"(a[3]), "r"(b0), "r"(b1))

#define GKC 16
#define SSTR 136   // (136*ktid+grp) mod 32 = 8*ktid+grp -> conflict-free

__global__ __launch_bounds__(256) void gemm_tc_kernel(const float* __restrict__ A1,
                                                      const float* __restrict__ A2,
                                                      const float* __restrict__ B,
                                                      const float* __restrict__ av,
                                                      int n, int mode, int b1i, int b2i) {
    __shared__ uint32_t Ah[GKC][SSTR], Al[GKC][SSTR];
    __shared__ uint32_t Bh[GKC][SSTR], Bl[GKC][SSTR];
    int tid  = threadIdx.x;
    int lane = tid & 31, warp = tid >> 5;
    int wm = warp >> 1, wn = warp & 1;          // warp tile: 32 rows x 64 cols
    int grp = lane >> 2, ktid = lane & 3;
    int row0 = blockIdx.x * 128;

    float acc[2][8][4];
#pragma unroll
    for (int t = 0; t < 2; t++)
#pragma unroll
        for (int j = 0; j < 8; j++)
#pragma unroll
            for (int q = 0; q < 4; q++) acc[t][j][q] = 0.f;

    int ar = tid & 127, aq = tid >> 7;          // A loader: row ar, col half aq
    int bkr = tid >> 4, bc = (tid & 15) * 8;    // B loader: k-row bkr, col bc

    for (int k0 = 0; k0 < HID; k0 += GKC) {
        // ---- stage A chunk [128 x GKC] with fused activation, split hi/lo ----
#pragma unroll
        for (int j = 0; j < 2; j++) {
            int kc = aq * 8 + j * 4;
            int c  = k0 + kc;
            float4 v = make_float4(0.f, 0.f, 0.f, 0.f);
            if (row0 + ar < n) {
                v = *(const float4*)&A1[(row0 + ar) * HID + c];
                if (mode >= 1) {
                    float4 sc = *(const float4*)&d_scs[b1i][c];
                    float4 sh = *(const float4*)&d_shs[b1i][c];
                    v.x = eluf(fmaf(v.x, sc.x, sh.x));
                    v.y = eluf(fmaf(v.y, sc.y, sh.y));
                    v.z = eluf(fmaf(v.z, sc.z, sh.z));
                    v.w = eluf(fmaf(v.w, sc.w, sh.w));
                    if (mode == 2) {
                        float4 v2  = *(const float4*)&A2[(row0 + ar) * HID + c];
                        float4 sc2 = *(const float4*)&d_scs[b2i][c];
                        float4 sh2 = *(const float4*)&d_shs[b2i][c];
                        v.x += eluf(fmaf(v2.x, sc2.x, sh2.x));
                        v.y += eluf(fmaf(v2.y, sc2.y, sh2.y));
                        v.z += eluf(fmaf(v2.z, sc2.z, sh2.z));
                        v.w += eluf(fmaf(v2.w, sc2.w, sh2.w));
                    }
                }
            }
            float fv[4] = {v.x, v.y, v.z, v.w};
#pragma unroll
            for (int e2 = 0; e2 < 4; e2++) {
                uint32_t hi = f2tf(fv[e2]);
                uint32_t lo = f2tf(fv[e2] - __uint_as_float(hi));
                Ah[kc + e2][ar] = hi;
                Al[kc + e2][ar] = lo;
            }
        }
        // ---- stage B chunk [GKC x 128], split hi/lo ----
#pragma unroll
        for (int j = 0; j < 2; j++) {
            float4 v = *(const float4*)&B[(k0 + bkr) * HID + bc + j * 4];
            float fv[4] = {v.x, v.y, v.z, v.w};
            uint4 hv, lv;
            uint32_t* hp = (uint32_t*)&hv;
            uint32_t* lp = (uint32_t*)&lv;
#pragma unroll
            for (int e2 = 0; e2 < 4; e2++) {
                hp[e2] = f2tf(fv[e2]);
                lp[e2] = f2tf(fv[e2] - __uint_as_float(hp[e2]));
            }
            *(uint4*)&Bh[bkr][bc + j * 4] = hv;
            *(uint4*)&Bl[bkr][bc + j * 4] = lv;
        }
        __syncthreads();

#pragma unroll
        for (int kk = 0; kk < GKC / 8; kk++) {
            uint32_t ah[2][4], al[2][4];
#pragma unroll
            for (int t = 0; t < 2; t++) {
                int m = wm * 32 + t * 16 + grp;
                ah[t][0] = Ah[kk * 8 + ktid][m];
                ah[t][1] = Ah[kk * 8 + ktid][m + 8];
                ah[t][2] = Ah[kk * 8 + ktid + 4][m];
                ah[t][3] = Ah[kk * 8 + ktid + 4][m + 8];
                al[t][0] = Al[kk * 8 + ktid][m];
                al[t][1] = Al[kk * 8 + ktid][m + 8];
                al[t][2] = Al[kk * 8 + ktid + 4][m];
                al[t][3] = Al[kk * 8 + ktid + 4][m + 8];
            }
#pragma unroll
            for (int j = 0; j < 8; j++) {
                int nn = wn * 64 + j * 8 + grp;
                uint32_t bh0 = Bh[kk * 8 + ktid][nn], bh1 = Bh[kk * 8 + ktid + 4][nn];
                uint32_t bl0 = Bl[kk * 8 + ktid][nn], bl1 = Bl[kk * 8 + ktid + 4][nn];
#pragma unroll
                for (int t = 0; t < 2; t++) {
                    MMA8(acc[t][j], ah[t], bh0, bh1);   // hi*hi
                    MMA8(acc[t][j], ah[t], bl0, bl1);   // hi*lo
                    MMA8(acc[t][j], al[t], bh0, bh1);   // lo*hi
                }
            }
        }
        __syncthreads();
    }

    // ---- write h tiles ----
#pragma unroll
    for (int t = 0; t < 2; t++) {
        int r0 = row0 + wm * 32 + t * 16 + grp;
#pragma unroll
        for (int j = 0; j < 8; j++) {
            int c = wn * 64 + j * 8 + ktid * 2;
            if (r0 < n)
                *(float2*)&d_h[r0 * HID + c] = make_float2(acc[t][j][0], acc[t][j][1]);
            if (r0 + 8 < n)
                *(float2*)&d_h[(r0 + 8) * HID + c] = make_float2(acc[t][j][2], acc[t][j][3]);
        }
    }

    // ---- fused attention epilogue: warp covers heads wn*4..wn*4+3, 32 rows ----
    // Per thread, head hh lives in fragments j0=2hh (col off ktid*2) and
    // j1=2hh+1 (col off 8+ktid*2); reduce over the 4 ktid lanes with shfl_xor.
#pragma unroll
    for (int hh = 0; hh < 4; hh++) {
        int head = wn * 4 + hh;
        const float* ap = av + head * 2 * D;
        int co = ktid * 2;
        float as00 = __ldg(&ap[co]),         as01 = __ldg(&ap[co + 1]);
        float as10 = __ldg(&ap[8 + co]),     as11 = __ldg(&ap[8 + co + 1]);
        float ad00 = __ldg(&ap[D + co]),     ad01 = __ldg(&ap[D + co + 1]);
        float ad10 = __ldg(&ap[D + 8 + co]), ad11 = __ldg(&ap[D + 8 + co + 1]);
        int j0 = hh * 2, j1 = j0 + 1;
#pragma unroll
        for (int t = 0; t < 2; t++) {
            float s0 = acc[t][j0][0] * as00 + acc[t][j0][1] * as01
                     + acc[t][j1][0] * as10 + acc[t][j1][1] * as11;
            float s8 = acc[t][j0][2] * as00 + acc[t][j0][3] * as01
                     + acc[t][j1][2] * as10 + acc[t][j1][3] * as11;
            float d0 = acc[t][j0][0] * ad00 + acc[t][j0][1] * ad01
                     + acc[t][j1][0] * ad10 + acc[t][j1][1] * ad11;
            float d8 = acc[t][j0][2] * ad00 + acc[t][j0][3] * ad01
                     + acc[t][j1][2] * ad10 + acc[t][j1][3] * ad11;
            s0 += __shfl_xor_sync(~0u, s0, 1);  s0 += __shfl_xor_sync(~0u, s0, 2);
            s8 += __shfl_xor_sync(~0u, s8, 1);  s8 += __shfl_xor_sync(~0u, s8, 2);
            d0 += __shfl_xor_sync(~0u, d0, 1);  d0 += __shfl_xor_sync(~0u, d0, 2);
            d8 += __shfl_xor_sync(~0u, d8, 1);  d8 += __shfl_xor_sync(~0u, d8, 2);
            if (ktid == 0) {
                int r0 = row0 + wm * 32 + t * 16 + grp;
                if (r0 < n) {
                    d_esrc[r0 * H + head] = s0;
                    d_edst[r0 * H + head] = d0;
                }
                if (r0 + 8 < n) {
                    d_esrc[(r0 + 8) * H + head] = s8;
                    d_edst[(r0 + 8) * H + head] = d8;
                }
            }
        }
    }
}

// ---------------- CSR construction (once per launch) -----------------------------
__global__ void hist_kernel(const int* __restrict__ ei, int e) {
    int t = blockIdx.x * blockDim.x + threadIdx.x;
    if (t < e) atomicAdd(&d_cursor[__ldg(&ei[e + t])], 1);
}

__global__ void scan_kernel(int n) {
    __shared__ int wsum[32];
    int tid = threadIdx.x;                 // 1024 threads, 1 block
    int lane = tid & 31, wid = tid >> 5;
    int chunk = (n + 1023) / 1024;
    int lo = tid * chunk;
    int hi = min(lo + chunk, n);
    int s = 0;
    for (int i = lo; i < hi; i++) s += d_cursor[i];
    int inc = s;
#pragma unroll
    for (int o = 1; o < 32; o <<= 1) {
        int v = __shfl_up_sync(~0u, inc, o);
        if (lane >= o) inc += v;
    }
    if (lane == 31) wsum[wid] = inc;
    __syncthreads();
    if (wid == 0) {
        int v = wsum[lane];
        int iv = v;
#pragma unroll
        for (int o = 1; o < 32; o <<= 1) {
            int u = __shfl_up_sync(~0u, iv, o);
            if (lane >= o) iv += u;
        }
        wsum[lane] = iv - v;
    }
    __syncthreads();
    int off = wsum[wid] + inc - s;
    for (int i = lo; i < hi; i++) {
        int c = d_cursor[i];
        d_rowptr[i] = off;
        d_cursor[i] = off;
        off += c;
    }
    if (hi == n) d_rowptr[n] = off;
}

__global__ void scatter_kernel(const int* __restrict__ ei, int e) {
    int t = blockIdx.x * blockDim.x + threadIdx.x;
    if (t >= e) return;
    int dst = __ldg(&ei[e + t]);
    int pos = atomicAdd(&d_cursor[dst], 1);
    d_csrc[pos] = __ldg(&ei[t]);
}

// ---------------- fused GAT aggregation: one warp per dst node -------------------
// Single pass (no softmax max: ratio is shift-invariant, exp finite here).
// Also accumulates per-channel BN sums via block reduction. (Round-8 form.)
__global__ __launch_bounds__(256) void agg_kernel(float* __restrict__ aggout, int n) {
    __shared__ float rsum[8][HID];
    int wid = threadIdx.x >> 5, lane = threadIdx.x & 31;
    int w = blockIdx.x * 8 + wid;
    int head = lane >> 2;
    float4 o = make_float4(0.f, 0.f, 0.f, 0.f);

    if (w < n) {
        int start = d_rowptr[w], end = d_rowptr[w + 1];
        float ed = d_edst[w * H + head];
        float4 acc = make_float4(0.f, 0.f, 0.f, 0.f);
        float den = 0.f;
        int i = start;
        for (; i + 2 <= end; i += 2) {               // 2 edges in flight
            int s0 = __ldg(&d_csrc[i]);
            int s1 = __ldg(&d_csrc[i + 1]);
            float e0 = d_esrc[s0 * H + head] + ed;
            float e1 = d_esrc[s1 * H + head] + ed;
            float4 h0 = *(const float4*)&d_h[s0 * HID + lane * 4];
            float4 h1 = *(const float4*)&d_h[s1 * HID + lane * 4];
            e0 = (e0 >= 0.f) ? e0 : ALPHA * e0;
            e1 = (e1 >= 0.f) ? e1 : ALPHA * e1;
            float w0 = __expf(e0), w1 = __expf(e1);
            acc.x = fmaf(h0.x, w0, fmaf(h1.x, w1, acc.x));
            acc.y = fmaf(h0.y, w0, fmaf(h1.y, w1, acc.y));
            acc.z = fmaf(h0.z, w0, fmaf(h1.z, w1, acc.z));
            acc.w = fmaf(h0.w, w0, fmaf(h1.w, w1, acc.w));
            den += w0 + w1;
        }
        if (i < end) {
            int s0 = __ldg(&d_csrc[i]);
            float e0 = d_esrc[s0 * H + head] + ed;
            float4 h0 = *(const float4*)&d_h[s0 * HID + lane * 4];
            e0 = (e0 >= 0.f) ? e0 : ALPHA * e0;
            float w0 = __expf(e0);
            acc.x = fmaf(h0.x, w0, acc.x);
            acc.y = fmaf(h0.y, w0, acc.y);
            acc.z = fmaf(h0.z, w0, acc.z);
            acc.w = fmaf(h0.w, w0, acc.w);
            den += w0;
        }
        float inv = 1.f / (den + 1e-16f);
        o = make_float4(acc.x * inv, acc.y * inv, acc.z * inv, acc.w * inv);
        *(float4*)&aggout[w * HID + lane * 4] = o;
    }

    // per-block BN stat reduction (zeros from inactive warps are harmless)
    *(float4*)&rsum[wid][lane * 4] = o;
    __syncthreads();
    if (threadIdx.x < HID) {
        int c = threadIdx.x;
        float s = 0.f, q = 0.f;
#pragma unroll
        for (int k = 0; k < 8; k++) {
            float v = rsum[k][c];
            s += v;
            q = fmaf(v, v, q);
        }
        atomicAdd(&d_gsum[c], s);
        atomicAdd(&d_gsq[c], q);
    }
}

// ---------------- fold BN stats into scale/shift, then re-zero the stats ---------
// (last reader resets, so the next agg always starts from zeros; globals are
//  zero-initialized at module load, and every call ends with bnpar #3's reset)
__global__ void bnpar_kernel(const float* __restrict__ g, const float* __restrict__ b,
                             int idx, float invn) {
    int c = threadIdx.x;
    float mu = d_gsum[c] * invn;
    float var = d_gsq[c] * invn - mu * mu;
    float sc = g[c] * rsqrtf(var + BN_EPS);
    d_scs[idx][c] = sc;
    d_shs[idx][c] = b[c] - mu * sc;
    d_gsum[c] = 0.f;
    d_gsq[c] = 0.f;
}

// ---------------- final output: out = bn3(agg3) ----------------------------------
__global__ void out_kernel(const float* __restrict__ agg, float* __restrict__ out, int n) {
    int t = blockIdx.x * blockDim.x + threadIdx.x;
    if (t >= n * (HID / 4)) return;
    float4 v  = ((const float4*)agg)[t];
    int c = (t * 4) & (HID - 1);
    float4 sc = *(const float4*)&d_scs[2][c];
    float4 sh = *(const float4*)&d_shs[2][c];
    ((float4*)out)[t] = make_float4(fmaf(v.x, sc.x, sh.x), fmaf(v.y, sc.y, sh.y),
                                    fmaf(v.z, sc.z, sh.z), fmaf(v.w, sc.w, sh.w));
}

// ---------------- host-side driver (single stream) -------------------------------
extern "C" void kernel_launch(void* const* d_in, const int* in_sizes, int n_in,
                              void* d_out, int out_size) {
    const float* x  = (const float*)d_in[0];
    const int*   ei = (const int*)  d_in[1];
    const float* W1 = (const float*)d_in[2];
    const float* a1 = (const float*)d_in[3];
    const float* W2 = (const float*)d_in[4];
    const float* a2 = (const float*)d_in[5];
    const float* W3 = (const float*)d_in[6];
    const float* a3 = (const float*)d_in[7];
    const float* g1 = (const float*)d_in[8];
    const float* b1 = (const float*)d_in[9];
    const float* g2 = (const float*)d_in[10];
    const float* b2 = (const float*)d_in[11];
    const float* g3 = (const float*)d_in[12];
    const float* b3 = (const float*)d_in[13];

    int n = in_sizes[0] / HID;
    int e = in_sizes[1] / 2;
    float invn = 1.f / (float)n;

    float* aggbase = nullptr;
    void* curp = nullptr;
    cudaGetSymbolAddress((void**)&aggbase, d_aggb);
    cudaGetSymbolAddress(&curp, d_cursor);
    float* agg1 = aggbase;
    float* agg2 = aggbase + (size_t)NMAX * HID;
    float* agg3 = aggbase + (size_t)2 * NMAX * HID;

    // ---- build dst-CSR once; reused by all 3 layers ----
    cudaMemsetAsync(curp, 0, n * sizeof(int));
    hist_kernel<<<(e + 255) / 256, 256>>>(ei, e);
    scan_kernel<<<1, 1024>>>(n);
    scatter_kernel<<<(e + 255) / 256, 256>>>(ei, e);

    int gblk = (n + 127) / 128;
    int wblk = (n + 7) / 8;

    // layer 1 (attn fused into GEMM epilogue)
    gemm_tc_kernel<<<gblk, 256>>>(x, nullptr, W1, a1, n, 0, 0, 0);
    agg_kernel<<<wblk, 256>>>(agg1, n);
    bnpar_kernel<<<1, HID>>>(g1, b1, 0, invn);
    // layer 2 (input = elu(bn1(agg1)) computed in GEMM loader)
    gemm_tc_kernel<<<gblk, 256>>>(agg1, nullptr, W2, a2, n, 1, 0, 0);
    agg_kernel<<<wblk, 256>>>(agg2, n);
    bnpar_kernel<<<1, HID>>>(g2, b2, 1, invn);
    // layer 3 (input = elu(bn1(agg1)) + elu(bn2(agg2)) in GEMM loader)
    gemm_tc_kernel<<<gblk, 256>>>(agg1, agg2, W3, a3, n, 2, 0, 1);
    agg_kernel<<<wblk, 256>>>(agg3, n);
    bnpar_kernel<<<1, HID>>>(g3, b3, 2, invn);
    out_kernel<<<(n * (HID / 4) + 255) / 256, 256>>>(agg3, (float*)d_out, n);
}